// round 8
// baseline (speedup 1.0000x reference)
#include <cuda_runtime.h>
#include <cstdint>
#include <cstdio>

// Problem constants (fixed by the reference)
#define Nn 100000
#define Ee 1600000
#define Hh 64
#define Gg 64

// ---------------- static device scratch (no allocations allowed) ----------------
__device__ int      g_cnt[Nn];        // per-row edge count
__device__ int      g_ptr[Nn + 1];    // CSR row pointers
__device__ int      g_fill[Nn];       // scatter cursors
__device__ float    g_dis[Nn];        // deg^{-1/2}
__device__ int      g_ccol[Ee];       // CSR col indices
__device__ float    g_cnorm[Ee];      // CSR edge weights (-dis[r]*dis[c])
__device__ float    g_T1 [Nn * Hh];
__device__ float    g_Tmp[Nn * Hh];
__device__ float    g_hpre[Nn * Hh];
__device__ float    g_h  [Nn * Hh];
__device__ float    g_sc [Nn * Hh];
__device__ float    g_Wc [192 * 64];
__device__ float    g_stats[128];     // [0:64) sum, [64:128) sumsq
__device__ float    g_ab[128];        // [0:64) scale a, [64:128) shift c
__device__ unsigned g_pool[Gg * 64];

// ---------------- helpers ----------------
__device__ __forceinline__ unsigned enc_f(float f) {
    unsigned u = __float_as_uint(f);
    return (u & 0x80000000u) ? ~u : (u | 0x80000000u);
}
__device__ __forceinline__ float dec_f(unsigned u) {
    return (u & 0x80000000u) ? __uint_as_float(u & 0x7FFFFFFFu) : __uint_as_float(~u);
}
__device__ __forceinline__ float lrelu(float x) { return x > 0.0f ? x : 0.01f * x; }

// ---------------- preprocessing: CSR build ----------------
// edge_index is int32, layout [2, E] row-major.
__global__ void count_kernel(const int* __restrict__ ei) {
    int i = blockIdx.x * blockDim.x + threadIdx.x;
    if (i >= Ee) return;
    atomicAdd(&g_cnt[ei[i]], 1);
}

// Single-block exclusive scan of g_cnt -> g_ptr, g_fill; also g_dis = cnt^{-1/2}.
__global__ void __launch_bounds__(1024) scan_kernel() {
    const int T = 1024;
    const int C = (Nn + T - 1) / T;  // 98
    int t = threadIdx.x;
    int base = t * C;
    int s = 0;
    for (int i = 0; i < C; i++) {
        int idx = base + i;
        if (idx < Nn) s += g_cnt[idx];
    }
    __shared__ int sh[T];
    sh[t] = s;
    __syncthreads();
    for (int off = 1; off < T; off <<= 1) {
        int v = (t >= off) ? sh[t - off] : 0;
        __syncthreads();
        sh[t] += v;
        __syncthreads();
    }
    int run = (t == 0) ? 0 : sh[t - 1];
    for (int i = 0; i < C; i++) {
        int idx = base + i;
        if (idx < Nn) {
            int cnt = g_cnt[idx];
            g_ptr[idx] = run;
            g_fill[idx] = run;
            g_dis[idx] = cnt > 0 ? rsqrtf((float)cnt) : 0.0f;
            run += cnt;
        }
    }
    if (t == T - 1) g_ptr[Nn] = run;  // == Ee
}

__global__ void scatter_kernel(const int* __restrict__ ei) {
    int i = blockIdx.x * blockDim.x + threadIdx.x;
    if (i >= Ee) return;
    int r = ei[i];
    int c = ei[Ee + i];
    int pos = atomicAdd(&g_fill[r], 1);
    g_ccol[pos] = c;
    g_cnorm[pos] = -g_dis[r] * g_dis[c];
}

// ---------------- CSR propagation: dst[r] = sum_e norm[e] * src[col[e]] ----------------
// 16 threads per row (one float4 each); unroll-4 on edges (R3-validated: 35 us).
__global__ void __launch_bounds__(256) prop_csr_kernel(const float* __restrict__ src,
                                                       float* __restrict__ dst) {
    int r = blockIdx.x * 16 + (threadIdx.x >> 4);
    int q = threadIdx.x & 15;
    if (r >= Nn) return;
    int s = g_ptr[r];
    int e = g_ptr[r + 1];
    const float4* __restrict__ src4 = reinterpret_cast<const float4*>(src);
    float4 acc = make_float4(0.f, 0.f, 0.f, 0.f);
    int i = s;
    for (; i + 4 <= e; i += 4) {
        int   c0 = __ldg(&g_ccol[i]),     c1 = __ldg(&g_ccol[i + 1]);
        int   c2 = __ldg(&g_ccol[i + 2]), c3 = __ldg(&g_ccol[i + 3]);
        float n0 = __ldg(&g_cnorm[i]),     n1 = __ldg(&g_cnorm[i + 1]);
        float n2 = __ldg(&g_cnorm[i + 2]), n3 = __ldg(&g_cnorm[i + 3]);
        float4 v0 = __ldg(&src4[c0 * 16 + q]);
        float4 v1 = __ldg(&src4[c1 * 16 + q]);
        float4 v2 = __ldg(&src4[c2 * 16 + q]);
        float4 v3 = __ldg(&src4[c3 * 16 + q]);
        acc.x += n0 * v0.x + n1 * v1.x + n2 * v2.x + n3 * v3.x;
        acc.y += n0 * v0.y + n1 * v1.y + n2 * v2.y + n3 * v3.y;
        acc.z += n0 * v0.z + n1 * v1.z + n2 * v2.z + n3 * v3.z;
        acc.w += n0 * v0.w + n1 * v1.w + n2 * v2.w + n3 * v3.w;
    }
    for (; i < e; i++) {
        int   c = __ldg(&g_ccol[i]);
        float n = __ldg(&g_cnorm[i]);
        float4 v = __ldg(&src4[c * 16 + q]);
        acc.x += n * v.x;
        acc.y += n * v.y;
        acc.z += n * v.z;
        acc.w += n * v.w;
    }
    reinterpret_cast<float4*>(dst)[r * 16 + q] = acc;
}

// ---------------- combined ChebConv weight ----------------
// out = Tx0@(W0 - W2) + Tx1@W1 + prop(Tx1)@(2*W2)
__global__ void combine_wc_kernel(const float* __restrict__ w) {
    int idx = blockIdx.x * blockDim.x + threadIdx.x;
    if (idx >= 192 * 64) return;
    int kk = idx >> 6, j = idx & 63;
    float v;
    if (kk < 64)        v = w[kk * 64 + j] - w[2 * 4096 + kk * 64 + j];
    else if (kk < 128)  v = w[4096 + (kk - 64) * 64 + j];
    else                v = 2.0f * w[2 * 4096 + (kk - 128) * 64 + j];
    g_Wc[idx] = v;
}

// ---------------- fused 3-term GEMM: out[r,:] = [s0|s1|s2][r,:] @ Wc + bias ----------------
// 512 threads, 128 rows/block, 4 threads/row (16 outputs each).
// X staged per-source into smem -> j-split causes NO duplicated global traffic.
// Dynamic smem: sW float4[3072] (48 KB) + sX float4[2048] (32 KB) = 80 KB.
__global__ void __launch_bounds__(512, 2) gemm3_kernel(const float* __restrict__ s0,
                                                       const float* __restrict__ s1,
                                                       const float* __restrict__ s2,
                                                       const float* __restrict__ bias,
                                                       float* __restrict__ out) {
    extern __shared__ float4 dsm[];
    float4* sW = dsm;          // [k (0..191)][j4 (0..15)]
    float4* sX = dsm + 3072;   // [row_loc (0..127)][k4 (0..15)]
    int tid = threadIdx.x;
    const float4* gW = reinterpret_cast<const float4*>(g_Wc);
#pragma unroll
    for (int i = 0; i < 6; i++) sW[tid + 512 * i] = gW[tid + 512 * i];

    int rl = tid >> 2;        // row within block
    int qd = tid & 3;         // output quarter (16 features)
    int r = blockIdx.x * 128 + rl;
    bool act = r < Nn;

    float4 acc[4];
    const float4* b4 = reinterpret_cast<const float4*>(bias);
#pragma unroll
    for (int j4 = 0; j4 < 4; j4++) acc[j4] = __ldg(&b4[qd * 4 + j4]);

    const float* srcs[3] = {s0, s1, s2};
    long gbase = (long)blockIdx.x * 2048;
#pragma unroll 1
    for (int s = 0; s < 3; s++) {
        __syncthreads();   // previous compute done before overwriting sX (also orders sW on s=0)
        const float4* src4 = reinterpret_cast<const float4*>(srcs[s]);
#pragma unroll
        for (int i = 0; i < 4; i++) {
            int li = tid + 512 * i;
            long gi = gbase + li;
            sX[li] = (gi < (long)Nn * 16) ? __ldg(&src4[gi]) : make_float4(0.f, 0.f, 0.f, 0.f);
        }
        __syncthreads();
#pragma unroll 1
        for (int k4 = 0; k4 < 16; k4++) {
            float4 v = sX[rl * 16 + k4];
            float vs[4] = {v.x, v.y, v.z, v.w};
#pragma unroll
            for (int kk = 0; kk < 4; kk++) {
                const float4* w0 = &sW[(s * 64 + k4 * 4 + kk) * 16 + qd * 4];
#pragma unroll
                for (int j4 = 0; j4 < 4; j4++) {
                    float4 w = w0[j4];
                    acc[j4].x += vs[kk] * w.x;
                    acc[j4].y += vs[kk] * w.y;
                    acc[j4].z += vs[kk] * w.z;
                    acc[j4].w += vs[kk] * w.w;
                }
            }
        }
    }
    if (act) {
        float4* po = reinterpret_cast<float4*>(out + (size_t)r * 64) + qd * 4;
#pragma unroll
        for (int j4 = 0; j4 < 4; j4++) po[j4] = acc[j4];
    }
}

// ---------------- shortcut GEMM: out = x @ W(64x64) + bias (same structure) ----------------
// Dynamic smem: sW float4[1024] (16 KB) + sX float4[2048] (32 KB) = 48 KB.
__global__ void __launch_bounds__(512, 2) gemm1_kernel(const float* __restrict__ s0,
                                                       const float* __restrict__ w,
                                                       const float* __restrict__ bias,
                                                       float* __restrict__ out) {
    extern __shared__ float4 dsm[];
    float4* sW = dsm;          // [k (0..63)][j4 (0..15)]
    float4* sX = dsm + 1024;
    int tid = threadIdx.x;
    const float4* gW = reinterpret_cast<const float4*>(w);
#pragma unroll
    for (int i = 0; i < 2; i++) sW[tid + 512 * i] = __ldg(&gW[tid + 512 * i]);

    int rl = tid >> 2;
    int qd = tid & 3;
    int r = blockIdx.x * 128 + rl;
    bool act = r < Nn;

    float4 acc[4];
    const float4* b4 = reinterpret_cast<const float4*>(bias);
#pragma unroll
    for (int j4 = 0; j4 < 4; j4++) acc[j4] = __ldg(&b4[qd * 4 + j4]);

    const float4* src4 = reinterpret_cast<const float4*>(s0);
    long gbase = (long)blockIdx.x * 2048;
#pragma unroll
    for (int i = 0; i < 4; i++) {
        int li = tid + 512 * i;
        long gi = gbase + li;
        sX[li] = (gi < (long)Nn * 16) ? __ldg(&src4[gi]) : make_float4(0.f, 0.f, 0.f, 0.f);
    }
    __syncthreads();

#pragma unroll 1
    for (int k4 = 0; k4 < 16; k4++) {
        float4 v = sX[rl * 16 + k4];
        float vs[4] = {v.x, v.y, v.z, v.w};
#pragma unroll
        for (int kk = 0; kk < 4; kk++) {
            const float4* w0 = &sW[(k4 * 4 + kk) * 16 + qd * 4];
#pragma unroll
            for (int j4 = 0; j4 < 4; j4++) {
                float4 ww = w0[j4];
                acc[j4].x += vs[kk] * ww.x;
                acc[j4].y += vs[kk] * ww.y;
                acc[j4].z += vs[kk] * ww.z;
                acc[j4].w += vs[kk] * ww.w;
            }
        }
    }
    if (act) {
        float4* po = reinterpret_cast<float4*>(out + (size_t)r * 64) + qd * 4;
#pragma unroll
        for (int j4 = 0; j4 < 4; j4++) po[j4] = acc[j4];
    }
}

// ---------------- BN statistics ----------------
__global__ void __launch_bounds__(256) stats_kernel(const float* __restrict__ h) {
    int j = threadIdx.x & 63;
    int r0 = blockIdx.x * 4 + (threadIdx.x >> 6);
    float s = 0.0f, s2 = 0.0f;
    for (int r = r0; r < Nn; r += gridDim.x * 4) {
        float v = h[(size_t)r * 64 + j];
        s += v;
        s2 += v * v;
    }
    __shared__ float sh[256], sh2[256];
    sh[threadIdx.x] = s;
    sh2[threadIdx.x] = s2;
    __syncthreads();
    if (threadIdx.x < 64) {
        float ts  = sh[threadIdx.x] + sh[threadIdx.x + 64] + sh[threadIdx.x + 128] + sh[threadIdx.x + 192];
        float ts2 = sh2[threadIdx.x] + sh2[threadIdx.x + 64] + sh2[threadIdx.x + 128] + sh2[threadIdx.x + 192];
        atomicAdd(&g_stats[j], ts);
        atomicAdd(&g_stats[64 + j], ts2);
    }
}

__global__ void finalize_kernel(const float* __restrict__ gamma,
                                const float* __restrict__ beta) {
    int j = threadIdx.x;
    if (j >= 64) return;
    float mu  = g_stats[j] * (1.0f / (float)Nn);
    float var = g_stats[64 + j] * (1.0f / (float)Nn) - mu * mu;
    var = fmaxf(var, 0.0f);
    float a = gamma[j] * rsqrtf(var + 1e-5f);
    g_ab[j] = a;
    g_ab[64 + j] = beta[j] - mu * a;
}

// ---------------- BN apply + LeakyReLU (layers 1 & 2) ----------------
__global__ void __launch_bounds__(256) apply_kernel(const float* __restrict__ hpre,
                                                    float* __restrict__ h) {
    int idx = blockIdx.x * blockDim.x + threadIdx.x;  // Nn*16 float4
    if (idx >= Nn * 16) return;
    int j4 = idx & 15;
    float4 a = reinterpret_cast<const float4*>(g_ab)[j4];
    float4 c = reinterpret_cast<const float4*>(g_ab + 64)[j4];
    float4 v = reinterpret_cast<const float4*>(hpre)[idx];
    float4 o;
    o.x = lrelu(v.x * a.x + c.x);
    o.y = lrelu(v.y * a.y + c.y);
    o.z = lrelu(v.z * a.z + c.z);
    o.w = lrelu(v.w * a.w + c.w);
    reinterpret_cast<float4*>(h)[idx] = o;
}

// ---------------- layer 3: BN apply + LeakyReLU + shortcut + segment_max pooling ----------------
__global__ void __launch_bounds__(256) apply3_pool_kernel(const int* __restrict__ batch,
                                                          const float* __restrict__ hpre,
                                                          const float* __restrict__ sc) {
    int idx = blockIdx.x * 256 + threadIdx.x;  // exactly Nn*16 = 6250 blocks
    int j4 = idx & 15;
    int r = idx >> 4;
    float4 a = reinterpret_cast<const float4*>(g_ab)[j4];
    float4 c = reinterpret_cast<const float4*>(g_ab + 64)[j4];
    float4 v = reinterpret_cast<const float4*>(hpre)[idx];
    float4 s = reinterpret_cast<const float4*>(sc)[idx];
    float4 h;
    h.x = lrelu(v.x * a.x + c.x) + s.x;
    h.y = lrelu(v.y * a.y + c.y) + s.y;
    h.z = lrelu(v.z * a.z + c.z) + s.z;
    h.w = lrelu(v.w * a.w + c.w) + s.w;

    __shared__ float4 sv[256];
    sv[threadIdx.x] = h;
    int row0 = blockIdx.x * 16;
    __syncthreads();

    int b0 = batch[row0];
    int bL = batch[row0 + 15];
    if (b0 == bL) {
        if (threadIdx.x < 64) {
            int slot = threadIdx.x;
            const float* svf = reinterpret_cast<const float*>(sv);
            float m = svf[slot];
#pragma unroll
            for (int rr = 1; rr < 16; rr++) m = fmaxf(m, svf[rr * 64 + slot]);
            atomicMax(&g_pool[b0 * 64 + slot], enc_f(m));
        }
    } else {
        int b = batch[r];
        atomicMax(&g_pool[b * 64 + j4 * 4 + 0], enc_f(h.x));
        atomicMax(&g_pool[b * 64 + j4 * 4 + 1], enc_f(h.y));
        atomicMax(&g_pool[b * 64 + j4 * 4 + 2], enc_f(h.z));
        atomicMax(&g_pool[b * 64 + j4 * 4 + 3], enc_f(h.w));
    }
}

// ---------------- final: out[g] = pooled[g,:] @ w_lin + b_lin ----------------
__global__ void final_kernel(const float* __restrict__ wl,
                             const float* __restrict__ bl,
                             float* __restrict__ out) {
    int g = blockIdx.x;
    int j = threadIdx.x;
    float v = dec_f(g_pool[g * 64 + j]) * wl[j];
    __shared__ float sred[64];
    sred[j] = v;
    __syncthreads();
    if (j < 32) {
        float t = sred[j] + sred[j + 32];
#pragma unroll
        for (int off = 16; off > 0; off >>= 1) t += __shfl_down_sync(0xFFFFFFFFu, t, off);
        if (j == 0) out[g] = t + bl[0];
    }
}

// ---------------- host launcher ----------------
extern "C" void kernel_launch(void* const* d_in, const int* in_sizes, int n_in,
                              void* d_out, int out_size) {
    (void)in_sizes; (void)n_in; (void)out_size;
    const float* x     = (const float*)d_in[0];
    const int*   ei    = (const int*)d_in[1];      // int32 (JAX x64 disabled)
    const int*   batch = (const int*)d_in[2];      // int32
    const float* w1 = (const float*)d_in[3];
    const float* b1 = (const float*)d_in[4];
    const float* w2 = (const float*)d_in[5];
    const float* b2 = (const float*)d_in[6];
    const float* w3 = (const float*)d_in[7];
    const float* b3 = (const float*)d_in[8];
    const float* g1 = (const float*)d_in[9];
    const float* be1 = (const float*)d_in[10];
    const float* g2 = (const float*)d_in[11];
    const float* be2 = (const float*)d_in[12];
    const float* g3 = (const float*)d_in[13];
    const float* be3 = (const float*)d_in[14];
    const float* w_sc = (const float*)d_in[15];
    const float* b_sc = (const float*)d_in[16];
    const float* w_lin = (const float*)d_in[17];
    const float* b_lin = (const float*)d_in[18];
    float* out = (float*)d_out;

    // Opt-in smem sizes (idempotent host calls; no allocation)
    static int smem_set = 0;
    if (!smem_set) {
        cudaFuncSetAttribute(gemm3_kernel, cudaFuncAttributeMaxDynamicSharedMemorySize, 81920);
        cudaFuncSetAttribute(gemm1_kernel, cudaFuncAttributeMaxDynamicSharedMemorySize, 49152);
        smem_set = 1;
    }

    void *p_cnt, *p_T1, *p_Tmp, *p_hpre, *p_h, *p_sc, *p_stats, *p_pool;
    cudaGetSymbolAddress(&p_cnt, g_cnt);
    cudaGetSymbolAddress(&p_T1, g_T1);
    cudaGetSymbolAddress(&p_Tmp, g_Tmp);
    cudaGetSymbolAddress(&p_hpre, g_hpre);
    cudaGetSymbolAddress(&p_h, g_h);
    cudaGetSymbolAddress(&p_sc, g_sc);
    cudaGetSymbolAddress(&p_stats, g_stats);
    cudaGetSymbolAddress(&p_pool, g_pool);

    const float* f_T1   = (const float*)p_T1;
    const float* f_Tmp  = (const float*)p_Tmp;
    const float* f_hpre = (const float*)p_hpre;
    const float* f_h    = (const float*)p_h;
    const float* f_sc   = (const float*)p_sc;

    const int EB = (Ee + 255) / 256;          // 6250
    const int GB = (Nn + 127) / 128;          // 782 (GEMMs: 128 rows/block)
    const int RB = Nn / 16;                   // 6250 (prop: 16 rows/block)
    const int AB = (Nn * 16 + 255) / 256;     // 6250

    // --- CSR build; gemm1 sits at profiled launch slot 5 ---
    cudaMemsetAsync(p_cnt, 0, Nn * sizeof(int));
    count_kernel<<<EB, 256>>>(ei);
    scan_kernel<<<1, 1024>>>();
    scatter_kernel<<<EB, 256>>>(ei);
    gemm1_kernel<<<GB, 512, 49152>>>(x, w_sc, b_sc, (float*)p_sc);
    cudaMemsetAsync(p_pool, 0, Gg * 64 * sizeof(unsigned));

    const float* layer_in = x;
    const float* Ws[3] = {w1, w2, w3};
    const float* Bs[3] = {b1, b2, b3};
    const float* Gs[3] = {g1, g2, g3};
    const float* BEs[3] = {be1, be2, be3};

    for (int L = 0; L < 3; L++) {
        prop_csr_kernel<<<RB, 256>>>(layer_in, (float*)p_T1);
        prop_csr_kernel<<<RB, 256>>>(f_T1, (float*)p_Tmp);
        combine_wc_kernel<<<48, 256>>>(Ws[L]);
        gemm3_kernel<<<GB, 512, 81920>>>(layer_in, f_T1, f_Tmp, Bs[L], (float*)p_hpre);
        cudaMemsetAsync(p_stats, 0, 128 * sizeof(float));
        stats_kernel<<<256, 256>>>(f_hpre);
        finalize_kernel<<<1, 64>>>(Gs[L], BEs[L]);
        if (L < 2) {
            apply_kernel<<<AB, 256>>>(f_hpre, (float*)p_h);
            layer_in = f_h;
        } else {
            apply3_pool_kernel<<<AB, 256>>>(batch, f_hpre, f_sc);
        }
    }

    final_kernel<<<Gg, 64>>>(w_lin, b_lin, out);
}

// round 9
// speedup vs baseline: 1.4324x; 1.4324x over previous
#include <cuda_runtime.h>
#include <cstdint>
#include <cstdio>

// Problem constants (fixed by the reference)
#define Nn 100000
#define Ee 1600000
#define Hh 64
#define Gg 64

// ---------------- static device scratch (no allocations allowed) ----------------
__device__ int      g_cnt[Nn];          // per-row edge count
__device__ int      g_ptr[Nn + 1];      // CSR row pointers
__device__ int      g_fill[Nn];         // scatter cursors
__device__ float    g_dis[Nn];          // deg^{-1/2}
__device__ int4     g_ccol4 [Ee / 4];   // CSR col indices (16B-aligned vector storage)
__device__ float4   g_cnorm4[Ee / 4];   // CSR edge weights (16B-aligned vector storage)
__device__ float    g_T1 [Nn * Hh];
__device__ float    g_Tmp[Nn * Hh];
__device__ float    g_hpre[Nn * Hh];
__device__ float    g_h  [Nn * Hh];
__device__ float    g_sc [Nn * Hh];
__device__ float    g_Wc [192 * 64];
__device__ float    g_stats[128];       // [0:64) sum, [64:128) sumsq
__device__ float    g_ab[128];          // [0:64) scale a, [64:128) shift c
__device__ unsigned g_pool[Gg * 64];

// ---------------- helpers ----------------
__device__ __forceinline__ unsigned enc_f(float f) {
    unsigned u = __float_as_uint(f);
    return (u & 0x80000000u) ? ~u : (u | 0x80000000u);
}
__device__ __forceinline__ float dec_f(unsigned u) {
    return (u & 0x80000000u) ? __uint_as_float(u & 0x7FFFFFFFu) : __uint_as_float(~u);
}
__device__ __forceinline__ float lrelu(float x) { return x > 0.0f ? x : 0.01f * x; }

// ---------------- preprocessing: CSR build ----------------
// edge_index is int32, layout [2, E] row-major.
__global__ void count_kernel(const int* __restrict__ ei) {
    int i = blockIdx.x * blockDim.x + threadIdx.x;
    if (i >= Ee) return;
    atomicAdd(&g_cnt[ei[i]], 1);
}

// Single-block exclusive scan of g_cnt -> g_ptr, g_fill; also g_dis = cnt^{-1/2}.
__global__ void __launch_bounds__(1024) scan_kernel() {
    const int T = 1024;
    const int C = (Nn + T - 1) / T;  // 98
    int t = threadIdx.x;
    int base = t * C;
    int s = 0;
    for (int i = 0; i < C; i++) {
        int idx = base + i;
        if (idx < Nn) s += g_cnt[idx];
    }
    __shared__ int sh[T];
    sh[t] = s;
    __syncthreads();
    for (int off = 1; off < T; off <<= 1) {
        int v = (t >= off) ? sh[t - off] : 0;
        __syncthreads();
        sh[t] += v;
        __syncthreads();
    }
    int run = (t == 0) ? 0 : sh[t - 1];
    for (int i = 0; i < C; i++) {
        int idx = base + i;
        if (idx < Nn) {
            int cnt = g_cnt[idx];
            g_ptr[idx] = run;
            g_fill[idx] = run;
            g_dis[idx] = cnt > 0 ? rsqrtf((float)cnt) : 0.0f;
            run += cnt;
        }
    }
    if (t == T - 1) g_ptr[Nn] = run;  // == Ee
}

__global__ void scatter_kernel(const int* __restrict__ ei) {
    int i = blockIdx.x * blockDim.x + threadIdx.x;
    if (i >= Ee) return;
    int r = ei[i];
    int c = ei[Ee + i];
    int pos = atomicAdd(&g_fill[r], 1);
    reinterpret_cast<int*>(g_ccol4)[pos] = c;
    reinterpret_cast<float*>(g_cnorm4)[pos] = -g_dis[r] * g_dis[c];
}

// ---------------- CSR propagation: dst[r] = sum_e norm[e] * src[col[e]] ----------------
// 16 threads per row (one float4 each); unroll-4 on edges with VECTOR loads of
// col/norm (aligned int4/float4) + scalar head/tail.
__global__ void __launch_bounds__(256) prop_csr_kernel(const float* __restrict__ src,
                                                       float* __restrict__ dst) {
    int r = blockIdx.x * 16 + (threadIdx.x >> 4);
    int q = threadIdx.x & 15;
    if (r >= Nn) return;
    int s = g_ptr[r];
    int e = g_ptr[r + 1];
    const int*   ccol  = reinterpret_cast<const int*>(g_ccol4);
    const float* cnorm = reinterpret_cast<const float*>(g_cnorm4);
    const float4* __restrict__ src4 = reinterpret_cast<const float4*>(src);
    float4 acc = make_float4(0.f, 0.f, 0.f, 0.f);

    int i = s;
    int a0 = (s + 3) & ~3;
    if (a0 > e) a0 = e;
    for (; i < a0; i++) {
        int   c = __ldg(&ccol[i]);
        float n = __ldg(&cnorm[i]);
        float4 v = __ldg(&src4[c * 16 + q]);
        acc.x += n * v.x; acc.y += n * v.y; acc.z += n * v.z; acc.w += n * v.w;
    }
    for (; i + 4 <= e; i += 4) {
        int4   cc = __ldg(&g_ccol4[i >> 2]);
        float4 nn = __ldg(&g_cnorm4[i >> 2]);
        float4 v0 = __ldg(&src4[cc.x * 16 + q]);
        float4 v1 = __ldg(&src4[cc.y * 16 + q]);
        float4 v2 = __ldg(&src4[cc.z * 16 + q]);
        float4 v3 = __ldg(&src4[cc.w * 16 + q]);
        acc.x += nn.x * v0.x + nn.y * v1.x + nn.z * v2.x + nn.w * v3.x;
        acc.y += nn.x * v0.y + nn.y * v1.y + nn.z * v2.y + nn.w * v3.y;
        acc.z += nn.x * v0.z + nn.y * v1.z + nn.z * v2.z + nn.w * v3.z;
        acc.w += nn.x * v0.w + nn.y * v1.w + nn.z * v2.w + nn.w * v3.w;
    }
    for (; i < e; i++) {
        int   c = __ldg(&ccol[i]);
        float n = __ldg(&cnorm[i]);
        float4 v = __ldg(&src4[c * 16 + q]);
        acc.x += n * v.x; acc.y += n * v.y; acc.z += n * v.z; acc.w += n * v.w;
    }
    reinterpret_cast<float4*>(dst)[r * 16 + q] = acc;
}

// ---------------- combined ChebConv weight ----------------
// out = Tx0@(W0 - W2) + Tx1@W1 + prop(Tx1)@(2*W2)
__global__ void combine_wc_kernel(const float* __restrict__ w) {
    int idx = blockIdx.x * blockDim.x + threadIdx.x;
    if (idx >= 192 * 64) return;
    int kk = idx >> 6, j = idx & 63;
    float v;
    if (kk < 64)        v = w[kk * 64 + j] - w[2 * 4096 + kk * 64 + j];
    else if (kk < 128)  v = w[4096 + (kk - 64) * 64 + j];
    else                v = 2.0f * w[2 * 4096 + (kk - 128) * 64 + j];
    g_Wc[idx] = v;
}

// ---------------- fused 3-term GEMM: out[r,:] = [s0|s1|s2][r,:] @ Wc + bias ----------------
// 512 threads, 128 rows/block, 4 threads/row. Conflict-free smem:
//  - sX rows padded to 17 float4 (272 B) -> 8 row-groups/warp hit distinct banks
//  - lane qd accumulates INTERLEAVED output float4s jj = j4*4+qd -> the 4 lanes
//    of a row read 64 consecutive bytes of sW per step (one 64B transaction)
// Dynamic smem: sW 3072 f4 (48 KB) + sX 128*17 f4 (34 KB) = 83968 B.
__global__ void __launch_bounds__(512, 2) gemm3_kernel(const float* __restrict__ s0,
                                                       const float* __restrict__ s1,
                                                       const float* __restrict__ s2,
                                                       const float* __restrict__ bias,
                                                       float* __restrict__ out) {
    extern __shared__ float4 dsm[];
    float4* sW = dsm;          // [k (0..191)][jj (0..15)]
    float4* sX = dsm + 3072;   // [row_loc (0..127)][k4 (0..15)], stride 17
    int tid = threadIdx.x;
    const float4* gW = reinterpret_cast<const float4*>(g_Wc);
#pragma unroll
    for (int i = 0; i < 6; i++) sW[tid + 512 * i] = gW[tid + 512 * i];

    int rl = tid >> 2;        // row within block
    int qd = tid & 3;         // lane's interleave slot
    int r = blockIdx.x * 128 + rl;
    bool act = r < Nn;

    float4 acc[4];            // outputs jj = j4*4+qd
    const float4* b4 = reinterpret_cast<const float4*>(bias);
#pragma unroll
    for (int j4 = 0; j4 < 4; j4++) acc[j4] = __ldg(&b4[j4 * 4 + qd]);

    const float* srcs[3] = {s0, s1, s2};
    long gbase = (long)blockIdx.x * 2048;
#pragma unroll 1
    for (int s = 0; s < 3; s++) {
        __syncthreads();   // previous compute done before overwriting sX
        const float4* src4 = reinterpret_cast<const float4*>(srcs[s]);
#pragma unroll
        for (int i = 0; i < 4; i++) {
            int li = tid + 512 * i;
            long gi = gbase + li;
            float4 v = (gi < (long)Nn * 16) ? __ldg(&src4[gi]) : make_float4(0.f, 0.f, 0.f, 0.f);
            sX[(li >> 4) * 17 + (li & 15)] = v;
        }
        __syncthreads();   // also orders sW writes before first compute
#pragma unroll 1
        for (int k4 = 0; k4 < 16; k4++) {
            float4 v = sX[rl * 17 + k4];
            float vs[4] = {v.x, v.y, v.z, v.w};
#pragma unroll
            for (int kk = 0; kk < 4; kk++) {
                const float4* w0 = &sW[(s * 64 + k4 * 4 + kk) * 16 + qd];
#pragma unroll
                for (int j4 = 0; j4 < 4; j4++) {
                    float4 w = w0[j4 * 4];   // address = base + (j4*4+qd) f4
                    acc[j4].x += vs[kk] * w.x;
                    acc[j4].y += vs[kk] * w.y;
                    acc[j4].z += vs[kk] * w.z;
                    acc[j4].w += vs[kk] * w.w;
                }
            }
        }
    }
    if (act) {
        float4* po = reinterpret_cast<float4*>(out + (size_t)r * 64);
#pragma unroll
        for (int j4 = 0; j4 < 4; j4++) po[j4 * 4 + qd] = acc[j4];
    }
}

// ---------------- shortcut GEMM: out = x @ W(64x64) + bias (same structure) ----------------
// Dynamic smem: sW 1024 f4 (16 KB) + sX 2176 f4 (34 KB) = 51200 B.
__global__ void __launch_bounds__(512, 2) gemm1_kernel(const float* __restrict__ s0,
                                                       const float* __restrict__ w,
                                                       const float* __restrict__ bias,
                                                       float* __restrict__ out) {
    extern __shared__ float4 dsm[];
    float4* sW = dsm;          // [k (0..63)][jj (0..15)]
    float4* sX = dsm + 1024;
    int tid = threadIdx.x;
    const float4* gW = reinterpret_cast<const float4*>(w);
#pragma unroll
    for (int i = 0; i < 2; i++) sW[tid + 512 * i] = __ldg(&gW[tid + 512 * i]);

    int rl = tid >> 2;
    int qd = tid & 3;
    int r = blockIdx.x * 128 + rl;
    bool act = r < Nn;

    float4 acc[4];
    const float4* b4 = reinterpret_cast<const float4*>(bias);
#pragma unroll
    for (int j4 = 0; j4 < 4; j4++) acc[j4] = __ldg(&b4[j4 * 4 + qd]);

    const float4* src4 = reinterpret_cast<const float4*>(s0);
    long gbase = (long)blockIdx.x * 2048;
#pragma unroll
    for (int i = 0; i < 4; i++) {
        int li = tid + 512 * i;
        long gi = gbase + li;
        float4 v = (gi < (long)Nn * 16) ? __ldg(&src4[gi]) : make_float4(0.f, 0.f, 0.f, 0.f);
        sX[(li >> 4) * 17 + (li & 15)] = v;
    }
    __syncthreads();

#pragma unroll 1
    for (int k4 = 0; k4 < 16; k4++) {
        float4 v = sX[rl * 17 + k4];
        float vs[4] = {v.x, v.y, v.z, v.w};
#pragma unroll
        for (int kk = 0; kk < 4; kk++) {
            const float4* w0 = &sW[(k4 * 4 + kk) * 16 + qd];
#pragma unroll
            for (int j4 = 0; j4 < 4; j4++) {
                float4 ww = w0[j4 * 4];
                acc[j4].x += vs[kk] * ww.x;
                acc[j4].y += vs[kk] * ww.y;
                acc[j4].z += vs[kk] * ww.z;
                acc[j4].w += vs[kk] * ww.w;
            }
        }
    }
    if (act) {
        float4* po = reinterpret_cast<float4*>(out + (size_t)r * 64);
#pragma unroll
        for (int j4 = 0; j4 < 4; j4++) po[j4 * 4 + qd] = acc[j4];
    }
}

// ---------------- BN statistics ----------------
__global__ void __launch_bounds__(256) stats_kernel(const float* __restrict__ h) {
    int j = threadIdx.x & 63;
    int r0 = blockIdx.x * 4 + (threadIdx.x >> 6);
    float s = 0.0f, s2 = 0.0f;
    for (int r = r0; r < Nn; r += gridDim.x * 4) {
        float v = h[(size_t)r * 64 + j];
        s += v;
        s2 += v * v;
    }
    __shared__ float sh[256], sh2[256];
    sh[threadIdx.x] = s;
    sh2[threadIdx.x] = s2;
    __syncthreads();
    if (threadIdx.x < 64) {
        float ts  = sh[threadIdx.x] + sh[threadIdx.x + 64] + sh[threadIdx.x + 128] + sh[threadIdx.x + 192];
        float ts2 = sh2[threadIdx.x] + sh2[threadIdx.x + 64] + sh2[threadIdx.x + 128] + sh2[threadIdx.x + 192];
        atomicAdd(&g_stats[j], ts);
        atomicAdd(&g_stats[64 + j], ts2);
    }
}

__global__ void finalize_kernel(const float* __restrict__ gamma,
                                const float* __restrict__ beta) {
    int j = threadIdx.x;
    if (j >= 64) return;
    float mu  = g_stats[j] * (1.0f / (float)Nn);
    float var = g_stats[64 + j] * (1.0f / (float)Nn) - mu * mu;
    var = fmaxf(var, 0.0f);
    float a = gamma[j] * rsqrtf(var + 1e-5f);
    g_ab[j] = a;
    g_ab[64 + j] = beta[j] - mu * a;
}

// ---------------- BN apply + LeakyReLU (layers 1 & 2) ----------------
__global__ void __launch_bounds__(256) apply_kernel(const float* __restrict__ hpre,
                                                    float* __restrict__ h) {
    int idx = blockIdx.x * blockDim.x + threadIdx.x;  // Nn*16 float4
    if (idx >= Nn * 16) return;
    int j4 = idx & 15;
    float4 a = reinterpret_cast<const float4*>(g_ab)[j4];
    float4 c = reinterpret_cast<const float4*>(g_ab + 64)[j4];
    float4 v = reinterpret_cast<const float4*>(hpre)[idx];
    float4 o;
    o.x = lrelu(v.x * a.x + c.x);
    o.y = lrelu(v.y * a.y + c.y);
    o.z = lrelu(v.z * a.z + c.z);
    o.w = lrelu(v.w * a.w + c.w);
    reinterpret_cast<float4*>(h)[idx] = o;
}

// ---------------- layer 3: BN apply + LeakyReLU + shortcut + segment_max pooling ----------------
__global__ void __launch_bounds__(256) apply3_pool_kernel(const int* __restrict__ batch,
                                                          const float* __restrict__ hpre,
                                                          const float* __restrict__ sc) {
    int idx = blockIdx.x * 256 + threadIdx.x;  // exactly Nn*16 = 6250 blocks
    int j4 = idx & 15;
    int r = idx >> 4;
    float4 a = reinterpret_cast<const float4*>(g_ab)[j4];
    float4 c = reinterpret_cast<const float4*>(g_ab + 64)[j4];
    float4 v = reinterpret_cast<const float4*>(hpre)[idx];
    float4 s = reinterpret_cast<const float4*>(sc)[idx];
    float4 h;
    h.x = lrelu(v.x * a.x + c.x) + s.x;
    h.y = lrelu(v.y * a.y + c.y) + s.y;
    h.z = lrelu(v.z * a.z + c.z) + s.z;
    h.w = lrelu(v.w * a.w + c.w) + s.w;

    __shared__ float4 sv[256];
    sv[threadIdx.x] = h;
    int row0 = blockIdx.x * 16;
    __syncthreads();

    int b0 = batch[row0];
    int bL = batch[row0 + 15];
    if (b0 == bL) {
        if (threadIdx.x < 64) {
            int slot = threadIdx.x;
            const float* svf = reinterpret_cast<const float*>(sv);
            float m = svf[slot];
#pragma unroll
            for (int rr = 1; rr < 16; rr++) m = fmaxf(m, svf[rr * 64 + slot]);
            atomicMax(&g_pool[b0 * 64 + slot], enc_f(m));
        }
    } else {
        int b = batch[r];
        atomicMax(&g_pool[b * 64 + j4 * 4 + 0], enc_f(h.x));
        atomicMax(&g_pool[b * 64 + j4 * 4 + 1], enc_f(h.y));
        atomicMax(&g_pool[b * 64 + j4 * 4 + 2], enc_f(h.z));
        atomicMax(&g_pool[b * 64 + j4 * 4 + 3], enc_f(h.w));
    }
}

// ---------------- final: out[g] = pooled[g,:] @ w_lin + b_lin ----------------
__global__ void final_kernel(const float* __restrict__ wl,
                             const float* __restrict__ bl,
                             float* __restrict__ out) {
    int g = blockIdx.x;
    int j = threadIdx.x;
    float v = dec_f(g_pool[g * 64 + j]) * wl[j];
    __shared__ float sred[64];
    sred[j] = v;
    __syncthreads();
    if (j < 32) {
        float t = sred[j] + sred[j + 32];
#pragma unroll
        for (int off = 16; off > 0; off >>= 1) t += __shfl_down_sync(0xFFFFFFFFu, t, off);
        if (j == 0) out[g] = t + bl[0];
    }
}

// ---------------- host launcher ----------------
extern "C" void kernel_launch(void* const* d_in, const int* in_sizes, int n_in,
                              void* d_out, int out_size) {
    (void)in_sizes; (void)n_in; (void)out_size;
    const float* x     = (const float*)d_in[0];
    const int*   ei    = (const int*)d_in[1];      // int32 (JAX x64 disabled)
    const int*   batch = (const int*)d_in[2];      // int32
    const float* w1 = (const float*)d_in[3];
    const float* b1 = (const float*)d_in[4];
    const float* w2 = (const float*)d_in[5];
    const float* b2 = (const float*)d_in[6];
    const float* w3 = (const float*)d_in[7];
    const float* b3 = (const float*)d_in[8];
    const float* g1 = (const float*)d_in[9];
    const float* be1 = (const float*)d_in[10];
    const float* g2 = (const float*)d_in[11];
    const float* be2 = (const float*)d_in[12];
    const float* g3 = (const float*)d_in[13];
    const float* be3 = (const float*)d_in[14];
    const float* w_sc = (const float*)d_in[15];
    const float* b_sc = (const float*)d_in[16];
    const float* w_lin = (const float*)d_in[17];
    const float* b_lin = (const float*)d_in[18];
    float* out = (float*)d_out;

    // Idempotent opt-in smem (immediate host-side call; graph-capture safe)
    cudaFuncSetAttribute(gemm3_kernel, cudaFuncAttributeMaxDynamicSharedMemorySize, 83968);
    cudaFuncSetAttribute(gemm1_kernel, cudaFuncAttributeMaxDynamicSharedMemorySize, 51200);

    void *p_cnt, *p_T1, *p_Tmp, *p_hpre, *p_h, *p_sc, *p_stats, *p_pool;
    cudaGetSymbolAddress(&p_cnt, g_cnt);
    cudaGetSymbolAddress(&p_T1, g_T1);
    cudaGetSymbolAddress(&p_Tmp, g_Tmp);
    cudaGetSymbolAddress(&p_hpre, g_hpre);
    cudaGetSymbolAddress(&p_h, g_h);
    cudaGetSymbolAddress(&p_sc, g_sc);
    cudaGetSymbolAddress(&p_stats, g_stats);
    cudaGetSymbolAddress(&p_pool, g_pool);

    const float* f_T1   = (const float*)p_T1;
    const float* f_Tmp  = (const float*)p_Tmp;
    const float* f_hpre = (const float*)p_hpre;
    const float* f_h    = (const float*)p_h;
    const float* f_sc   = (const float*)p_sc;

    const int EB = (Ee + 255) / 256;          // 6250
    const int GB = (Nn + 127) / 128;          // 782 (GEMMs: 128 rows/block)
    const int RB = Nn / 16;                   // 6250 (prop: 16 rows/block)
    const int AB = (Nn * 16 + 255) / 256;     // 6250

    // --- CSR build; gemm1 sits at profiled launch slot 5 ---
    cudaMemsetAsync(p_cnt, 0, Nn * sizeof(int));
    count_kernel<<<EB, 256>>>(ei);
    scan_kernel<<<1, 1024>>>();
    scatter_kernel<<<EB, 256>>>(ei);
    gemm1_kernel<<<GB, 512, 51200>>>(x, w_sc, b_sc, (float*)p_sc);
    cudaMemsetAsync(p_pool, 0, Gg * 64 * sizeof(unsigned));

    const float* layer_in = x;
    const float* Ws[3] = {w1, w2, w3};
    const float* Bs[3] = {b1, b2, b3};
    const float* Gs[3] = {g1, g2, g3};
    const float* BEs[3] = {be1, be2, be3};

    for (int L = 0; L < 3; L++) {
        prop_csr_kernel<<<RB, 256>>>(layer_in, (float*)p_T1);
        prop_csr_kernel<<<RB, 256>>>(f_T1, (float*)p_Tmp);
        combine_wc_kernel<<<48, 256>>>(Ws[L]);
        gemm3_kernel<<<GB, 512, 83968>>>(layer_in, f_T1, f_Tmp, Bs[L], (float*)p_hpre);
        cudaMemsetAsync(p_stats, 0, 128 * sizeof(float));
        stats_kernel<<<256, 256>>>(f_hpre);
        finalize_kernel<<<1, 64>>>(Gs[L], BEs[L]);
        if (L < 2) {
            apply_kernel<<<AB, 256>>>(f_hpre, (float*)p_h);
            layer_in = f_h;
        } else {
            apply3_pool_kernel<<<AB, 256>>>(batch, f_hpre, f_sc);
        }
    }

    final_kernel<<<Gg, 64>>>(w_lin, b_lin, out);
}

// round 10
// speedup vs baseline: 1.7388x; 1.2138x over previous
#include <cuda_runtime.h>
#include <cstdint>
#include <cstdio>

// Problem constants (fixed by the reference)
#define Nn 100000
#define Ee 1600000
#define Hh 64
#define Gg 64

// ---------------- static device scratch (no allocations allowed) ----------------
__device__ int      g_cnt[Nn];          // per-row edge count
__device__ int      g_ptr[Nn + 1];      // CSR row pointers
__device__ int      g_fill[Nn];         // scatter cursors
__device__ float    g_dis[Nn];          // deg^{-1/2}
__device__ int4     g_ccol4 [Ee / 4];   // CSR col indices (16B-aligned storage)
__device__ float4   g_cnorm4[Ee / 4];   // CSR edge weights (16B-aligned storage)
__device__ float    g_T1 [Nn * Hh];
__device__ float    g_Tmp[Nn * Hh];
__device__ float    g_hpre[Nn * Hh];
__device__ float    g_h  [Nn * Hh];
__device__ float    g_sc [Nn * Hh];
__device__ float    g_Wc [192 * 64];
__device__ float    g_stats[128];       // [0:64) sum, [64:128) sumsq
__device__ float    g_ab[128];          // [0:64) scale a, [64:128) shift c
__device__ unsigned g_pool[Gg * 64];

// ---------------- helpers ----------------
__device__ __forceinline__ unsigned enc_f(float f) {
    unsigned u = __float_as_uint(f);
    return (u & 0x80000000u) ? ~u : (u | 0x80000000u);
}
__device__ __forceinline__ float dec_f(unsigned u) {
    return (u & 0x80000000u) ? __uint_as_float(u & 0x7FFFFFFFu) : __uint_as_float(~u);
}
__device__ __forceinline__ float lrelu(float x) { return x > 0.0f ? x : 0.01f * x; }

// ---------------- preprocessing: CSR build ----------------
// edge_index is int32, layout [2, E] row-major.
__global__ void count_kernel(const int* __restrict__ ei) {
    int i = blockIdx.x * blockDim.x + threadIdx.x;
    if (i >= Ee) return;
    atomicAdd(&g_cnt[ei[i]], 1);
}

// Single-block exclusive scan of g_cnt -> g_ptr, g_fill; also g_dis = cnt^{-1/2}.
__global__ void __launch_bounds__(1024) scan_kernel() {
    const int T = 1024;
    const int C = (Nn + T - 1) / T;  // 98
    int t = threadIdx.x;
    int base = t * C;
    int s = 0;
    for (int i = 0; i < C; i++) {
        int idx = base + i;
        if (idx < Nn) s += g_cnt[idx];
    }
    __shared__ int sh[T];
    sh[t] = s;
    __syncthreads();
    for (int off = 1; off < T; off <<= 1) {
        int v = (t >= off) ? sh[t - off] : 0;
        __syncthreads();
        sh[t] += v;
        __syncthreads();
    }
    int run = (t == 0) ? 0 : sh[t - 1];
    for (int i = 0; i < C; i++) {
        int idx = base + i;
        if (idx < Nn) {
            int cnt = g_cnt[idx];
            g_ptr[idx] = run;
            g_fill[idx] = run;
            g_dis[idx] = cnt > 0 ? rsqrtf((float)cnt) : 0.0f;
            run += cnt;
        }
    }
    if (t == T - 1) g_ptr[Nn] = run;  // == Ee
}

__global__ void scatter_kernel(const int* __restrict__ ei) {
    int i = blockIdx.x * blockDim.x + threadIdx.x;
    if (i >= Ee) return;
    int r = ei[i];
    int c = ei[Ee + i];
    int pos = atomicAdd(&g_fill[r], 1);
    reinterpret_cast<int*>(g_ccol4)[pos] = c;
    reinterpret_cast<float*>(g_cnorm4)[pos] = -g_dis[r] * g_dis[c];
}

// ---------------- CSR propagation: dst[r] = sum_e norm[e] * src[col[e]] ----------------
// 16 threads per row (one float4 each); unroll-4 on edges with VECTOR loads
// of col/norm (aligned int4/float4), scalar head/tail.
__global__ void __launch_bounds__(256) prop_csr_kernel(const float* __restrict__ src,
                                                       float* __restrict__ dst) {
    int r = blockIdx.x * 16 + (threadIdx.x >> 4);
    int q = threadIdx.x & 15;
    if (r >= Nn) return;
    int s = g_ptr[r];
    int e = g_ptr[r + 1];
    const int*   ccol  = reinterpret_cast<const int*>(g_ccol4);
    const float* cnorm = reinterpret_cast<const float*>(g_cnorm4);
    const float4* __restrict__ src4 = reinterpret_cast<const float4*>(src);
    float4 acc = make_float4(0.f, 0.f, 0.f, 0.f);

    int i = s;
    int a0 = (s + 3) & ~3;
    if (a0 > e) a0 = e;
    for (; i < a0; i++) {
        int   c = __ldg(&ccol[i]);
        float n = __ldg(&cnorm[i]);
        float4 v = __ldg(&src4[c * 16 + q]);
        acc.x += n * v.x; acc.y += n * v.y; acc.z += n * v.z; acc.w += n * v.w;
    }
    for (; i + 4 <= e; i += 4) {
        int4   cc = __ldg(&g_ccol4[i >> 2]);
        float4 nn = __ldg(&g_cnorm4[i >> 2]);
        float4 v0 = __ldg(&src4[cc.x * 16 + q]);
        float4 v1 = __ldg(&src4[cc.y * 16 + q]);
        float4 v2 = __ldg(&src4[cc.z * 16 + q]);
        float4 v3 = __ldg(&src4[cc.w * 16 + q]);
        acc.x += nn.x * v0.x + nn.y * v1.x + nn.z * v2.x + nn.w * v3.x;
        acc.y += nn.x * v0.y + nn.y * v1.y + nn.z * v2.y + nn.w * v3.y;
        acc.z += nn.x * v0.z + nn.y * v1.z + nn.z * v2.z + nn.w * v3.z;
        acc.w += nn.x * v0.w + nn.y * v1.w + nn.z * v2.w + nn.w * v3.w;
    }
    for (; i < e; i++) {
        int   c = __ldg(&ccol[i]);
        float n = __ldg(&cnorm[i]);
        float4 v = __ldg(&src4[c * 16 + q]);
        acc.x += n * v.x; acc.y += n * v.y; acc.z += n * v.z; acc.w += n * v.w;
    }
    reinterpret_cast<float4*>(dst)[r * 16 + q] = acc;
}

// ---------------- combined ChebConv weight ----------------
// out = Tx0@(W0 - W2) + Tx1@W1 + prop(Tx1)@(2*W2)
__global__ void combine_wc_kernel(const float* __restrict__ w) {
    int idx = blockIdx.x * blockDim.x + threadIdx.x;
    if (idx >= 192 * 64) return;
    int kk = idx >> 6, j = idx & 63;
    float v;
    if (kk < 64)        v = w[kk * 64 + j] - w[2 * 4096 + kk * 64 + j];
    else if (kk < 128)  v = w[4096 + (kk - 64) * 64 + j];
    else                v = 2.0f * w[2 * 4096 + (kk - 128) * 64 + j];
    g_Wc[idx] = v;
}

// ---------------- fused 3-term GEMM (R3-proven): out = [s0|s1|s2] @ Wc + bias ----------------
// 1 thread per row, W in smem read as float4 (LDS.128 broadcast).
__global__ void __launch_bounds__(256) gemm3_kernel(const float* __restrict__ s0,
                                                    const float* __restrict__ s1,
                                                    const float* __restrict__ s2,
                                                    const float* __restrict__ bias,
                                                    float* __restrict__ out) {
    __shared__ float4 sW[192 * 16];  // 48 KB
    int tid = threadIdx.x;
    const float4* gW = reinterpret_cast<const float4*>(g_Wc);
#pragma unroll
    for (int i = 0; i < 12; i++) sW[tid + 256 * i] = gW[tid + 256 * i];
    __syncthreads();

    int r = blockIdx.x * 256 + tid;
    if (r >= Nn) return;

    float4 acc[16];
    const float4* b4 = reinterpret_cast<const float4*>(bias);
#pragma unroll
    for (int j4 = 0; j4 < 16; j4++) acc[j4] = __ldg(&b4[j4]);

    const float* srcs[3] = {s0, s1, s2};
#pragma unroll
    for (int s = 0; s < 3; s++) {
        const float4* p = reinterpret_cast<const float4*>(srcs[s] + (size_t)r * 64);
#pragma unroll 1
        for (int k4 = 0; k4 < 16; k4++) {
            float4 v = __ldg(&p[k4]);
            const float4* w = &sW[(s * 64 + k4 * 4) * 16];
#pragma unroll
            for (int j4 = 0; j4 < 16; j4++) {
                float4 wa = w[j4];
                float4 wb = w[16 + j4];
                float4 wc = w[32 + j4];
                float4 wd = w[48 + j4];
                acc[j4].x += v.x * wa.x + v.y * wb.x + v.z * wc.x + v.w * wd.x;
                acc[j4].y += v.x * wa.y + v.y * wb.y + v.z * wc.y + v.w * wd.y;
                acc[j4].z += v.x * wa.z + v.y * wb.z + v.z * wc.z + v.w * wd.z;
                acc[j4].w += v.x * wa.w + v.y * wb.w + v.z * wc.w + v.w * wd.w;
            }
        }
    }
    float4* po = reinterpret_cast<float4*>(out + (size_t)r * 64);
#pragma unroll
    for (int j4 = 0; j4 < 16; j4++) po[j4] = acc[j4];
}

// ---------------- shortcut GEMM (R3-proven): out = x @ W(64x64) + bias ----------------
__global__ void __launch_bounds__(256) gemm1_kernel(const float* __restrict__ s0,
                                                    const float* __restrict__ w,
                                                    const float* __restrict__ bias,
                                                    float* __restrict__ out) {
    __shared__ float4 sW[64 * 16];  // 16 KB
    int tid = threadIdx.x;
    const float4* gW = reinterpret_cast<const float4*>(w);
#pragma unroll
    for (int i = 0; i < 4; i++) sW[tid + 256 * i] = __ldg(&gW[tid + 256 * i]);
    __syncthreads();

    int r = blockIdx.x * 256 + tid;
    if (r >= Nn) return;

    float4 acc[16];
    const float4* b4 = reinterpret_cast<const float4*>(bias);
#pragma unroll
    for (int j4 = 0; j4 < 16; j4++) acc[j4] = __ldg(&b4[j4]);

    const float4* p = reinterpret_cast<const float4*>(s0 + (size_t)r * 64);
#pragma unroll 1
    for (int k4 = 0; k4 < 16; k4++) {
        float4 v = __ldg(&p[k4]);
        const float4* w0 = &sW[(k4 * 4) * 16];
#pragma unroll
        for (int j4 = 0; j4 < 16; j4++) {
            float4 wa = w0[j4];
            float4 wb = w0[16 + j4];
            float4 wc = w0[32 + j4];
            float4 wd = w0[48 + j4];
            acc[j4].x += v.x * wa.x + v.y * wb.x + v.z * wc.x + v.w * wd.x;
            acc[j4].y += v.x * wa.y + v.y * wb.y + v.z * wc.y + v.w * wd.y;
            acc[j4].z += v.x * wa.z + v.y * wb.z + v.z * wc.z + v.w * wd.z;
            acc[j4].w += v.x * wa.w + v.y * wb.w + v.z * wc.w + v.w * wd.w;
        }
    }
    float4* po = reinterpret_cast<float4*>(out + (size_t)r * 64);
#pragma unroll
    for (int j4 = 0; j4 < 16; j4++) po[j4] = acc[j4];
}

// ---------------- BN statistics (vectorized float4 loads) ----------------
// Thread (rg, j4): rg = tid>>4 strides rows, j4 = tid&15 is a fixed float4 column.
__global__ void __launch_bounds__(256) stats_kernel(const float* __restrict__ h) {
    int j4 = threadIdx.x & 15;
    int rg = threadIdx.x >> 4;
    const float4* h4 = reinterpret_cast<const float4*>(h);
    float4 s  = make_float4(0.f, 0.f, 0.f, 0.f);
    float4 s2 = make_float4(0.f, 0.f, 0.f, 0.f);
    for (int r = blockIdx.x * 16 + rg; r < Nn; r += gridDim.x * 16) {
        float4 v = __ldg(&h4[(size_t)r * 16 + j4]);
        s.x += v.x; s.y += v.y; s.z += v.z; s.w += v.w;
        s2.x += v.x * v.x; s2.y += v.y * v.y; s2.z += v.z * v.z; s2.w += v.w * v.w;
    }
    __shared__ float4 sh[256], sh2[256];
    sh[threadIdx.x] = s;
    sh2[threadIdx.x] = s2;
    __syncthreads();
#pragma unroll
    for (int off = 128; off >= 16; off >>= 1) {
        if (threadIdx.x < off) {
            float4 a = sh[threadIdx.x + off];
            sh[threadIdx.x].x += a.x; sh[threadIdx.x].y += a.y;
            sh[threadIdx.x].z += a.z; sh[threadIdx.x].w += a.w;
            float4 b = sh2[threadIdx.x + off];
            sh2[threadIdx.x].x += b.x; sh2[threadIdx.x].y += b.y;
            sh2[threadIdx.x].z += b.z; sh2[threadIdx.x].w += b.w;
        }
        __syncthreads();
    }
    if (threadIdx.x < 16) {
        float4 ts  = sh[threadIdx.x];
        float4 ts2 = sh2[threadIdx.x];
        int f = threadIdx.x * 4;
        atomicAdd(&g_stats[f + 0], ts.x);
        atomicAdd(&g_stats[f + 1], ts.y);
        atomicAdd(&g_stats[f + 2], ts.z);
        atomicAdd(&g_stats[f + 3], ts.w);
        atomicAdd(&g_stats[64 + f + 0], ts2.x);
        atomicAdd(&g_stats[64 + f + 1], ts2.y);
        atomicAdd(&g_stats[64 + f + 2], ts2.z);
        atomicAdd(&g_stats[64 + f + 3], ts2.w);
    }
}

__global__ void finalize_kernel(const float* __restrict__ gamma,
                                const float* __restrict__ beta) {
    int j = threadIdx.x;
    if (j >= 64) return;
    float mu  = g_stats[j] * (1.0f / (float)Nn);
    float var = g_stats[64 + j] * (1.0f / (float)Nn) - mu * mu;
    var = fmaxf(var, 0.0f);
    float a = gamma[j] * rsqrtf(var + 1e-5f);
    g_ab[j] = a;
    g_ab[64 + j] = beta[j] - mu * a;
}

// ---------------- BN apply + LeakyReLU (layers 1 & 2) ----------------
__global__ void __launch_bounds__(256) apply_kernel(const float* __restrict__ hpre,
                                                    float* __restrict__ h) {
    int idx = blockIdx.x * blockDim.x + threadIdx.x;  // Nn*16 float4
    if (idx >= Nn * 16) return;
    int j4 = idx & 15;
    float4 a = reinterpret_cast<const float4*>(g_ab)[j4];
    float4 c = reinterpret_cast<const float4*>(g_ab + 64)[j4];
    float4 v = reinterpret_cast<const float4*>(hpre)[idx];
    float4 o;
    o.x = lrelu(v.x * a.x + c.x);
    o.y = lrelu(v.y * a.y + c.y);
    o.z = lrelu(v.z * a.z + c.z);
    o.w = lrelu(v.w * a.w + c.w);
    reinterpret_cast<float4*>(h)[idx] = o;
}

// ---------------- layer 3: BN apply + LeakyReLU + shortcut + segment_max pooling ----------------
__global__ void __launch_bounds__(256) apply3_pool_kernel(const int* __restrict__ batch,
                                                          const float* __restrict__ hpre,
                                                          const float* __restrict__ sc) {
    int idx = blockIdx.x * 256 + threadIdx.x;  // exactly Nn*16 = 6250 blocks
    int j4 = idx & 15;
    int r = idx >> 4;
    float4 a = reinterpret_cast<const float4*>(g_ab)[j4];
    float4 c = reinterpret_cast<const float4*>(g_ab + 64)[j4];
    float4 v = reinterpret_cast<const float4*>(hpre)[idx];
    float4 s = reinterpret_cast<const float4*>(sc)[idx];
    float4 h;
    h.x = lrelu(v.x * a.x + c.x) + s.x;
    h.y = lrelu(v.y * a.y + c.y) + s.y;
    h.z = lrelu(v.z * a.z + c.z) + s.z;
    h.w = lrelu(v.w * a.w + c.w) + s.w;

    __shared__ float4 sv[256];
    sv[threadIdx.x] = h;
    int row0 = blockIdx.x * 16;
    __syncthreads();

    int b0 = batch[row0];
    int bL = batch[row0 + 15];
    if (b0 == bL) {
        if (threadIdx.x < 64) {
            int slot = threadIdx.x;
            const float* svf = reinterpret_cast<const float*>(sv);
            float m = svf[slot];
#pragma unroll
            for (int rr = 1; rr < 16; rr++) m = fmaxf(m, svf[rr * 64 + slot]);
            atomicMax(&g_pool[b0 * 64 + slot], enc_f(m));
        }
    } else {
        int b = batch[r];
        atomicMax(&g_pool[b * 64 + j4 * 4 + 0], enc_f(h.x));
        atomicMax(&g_pool[b * 64 + j4 * 4 + 1], enc_f(h.y));
        atomicMax(&g_pool[b * 64 + j4 * 4 + 2], enc_f(h.z));
        atomicMax(&g_pool[b * 64 + j4 * 4 + 3], enc_f(h.w));
    }
}

// ---------------- final: out[g] = pooled[g,:] @ w_lin + b_lin ----------------
__global__ void final_kernel(const float* __restrict__ wl,
                             const float* __restrict__ bl,
                             float* __restrict__ out) {
    int g = blockIdx.x;
    int j = threadIdx.x;
    float v = dec_f(g_pool[g * 64 + j]) * wl[j];
    __shared__ float sred[64];
    sred[j] = v;
    __syncthreads();
    if (j < 32) {
        float t = sred[j] + sred[j + 32];
#pragma unroll
        for (int off = 16; off > 0; off >>= 1) t += __shfl_down_sync(0xFFFFFFFFu, t, off);
        if (j == 0) out[g] = t + bl[0];
    }
}

// ---------------- host launcher ----------------
extern "C" void kernel_launch(void* const* d_in, const int* in_sizes, int n_in,
                              void* d_out, int out_size) {
    (void)in_sizes; (void)n_in; (void)out_size;
    const float* x     = (const float*)d_in[0];
    const int*   ei    = (const int*)d_in[1];      // int32 (JAX x64 disabled)
    const int*   batch = (const int*)d_in[2];      // int32
    const float* w1 = (const float*)d_in[3];
    const float* b1 = (const float*)d_in[4];
    const float* w2 = (const float*)d_in[5];
    const float* b2 = (const float*)d_in[6];
    const float* w3 = (const float*)d_in[7];
    const float* b3 = (const float*)d_in[8];
    const float* g1 = (const float*)d_in[9];
    const float* be1 = (const float*)d_in[10];
    const float* g2 = (const float*)d_in[11];
    const float* be2 = (const float*)d_in[12];
    const float* g3 = (const float*)d_in[13];
    const float* be3 = (const float*)d_in[14];
    const float* w_sc = (const float*)d_in[15];
    const float* b_sc = (const float*)d_in[16];
    const float* w_lin = (const float*)d_in[17];
    const float* b_lin = (const float*)d_in[18];
    float* out = (float*)d_out;

    void *p_cnt, *p_T1, *p_Tmp, *p_hpre, *p_h, *p_sc, *p_stats, *p_pool;
    cudaGetSymbolAddress(&p_cnt, g_cnt);
    cudaGetSymbolAddress(&p_T1, g_T1);
    cudaGetSymbolAddress(&p_Tmp, g_Tmp);
    cudaGetSymbolAddress(&p_hpre, g_hpre);
    cudaGetSymbolAddress(&p_h, g_h);
    cudaGetSymbolAddress(&p_sc, g_sc);
    cudaGetSymbolAddress(&p_stats, g_stats);
    cudaGetSymbolAddress(&p_pool, g_pool);

    const float* f_T1   = (const float*)p_T1;
    const float* f_Tmp  = (const float*)p_Tmp;
    const float* f_hpre = (const float*)p_hpre;
    const float* f_h    = (const float*)p_h;
    const float* f_sc   = (const float*)p_sc;

    const int EB = (Ee + 255) / 256;          // 6250
    const int NB = (Nn + 255) / 256;          // 391
    const int RB = Nn / 16;                   // 6250 (prop: 16 rows/block)
    const int AB = (Nn * 16 + 255) / 256;     // 6250

    // --- CSR build; first prop sits at profiled launch slot 5 ---
    cudaMemsetAsync(p_cnt, 0, Nn * sizeof(int));
    count_kernel<<<EB, 256>>>(ei);
    scan_kernel<<<1, 1024>>>();
    scatter_kernel<<<EB, 256>>>(ei);
    prop_csr_kernel<<<RB, 256>>>(x, (float*)p_T1);   // layer-1 prop #1 (slot 5)
    gemm1_kernel<<<NB, 256>>>(x, w_sc, b_sc, (float*)p_sc);
    cudaMemsetAsync(p_pool, 0, Gg * 64 * sizeof(unsigned));

    const float* layer_in = x;
    const float* Ws[3] = {w1, w2, w3};
    const float* Bs[3] = {b1, b2, b3};
    const float* Gs[3] = {g1, g2, g3};
    const float* BEs[3] = {be1, be2, be3};

    for (int L = 0; L < 3; L++) {
        if (L > 0) prop_csr_kernel<<<RB, 256>>>(layer_in, (float*)p_T1);
        prop_csr_kernel<<<RB, 256>>>(f_T1, (float*)p_Tmp);
        combine_wc_kernel<<<48, 256>>>(Ws[L]);
        gemm3_kernel<<<NB, 256>>>(layer_in, f_T1, f_Tmp, Bs[L], (float*)p_hpre);
        cudaMemsetAsync(p_stats, 0, 128 * sizeof(float));
        stats_kernel<<<256, 256>>>(f_hpre);
        finalize_kernel<<<1, 64>>>(Gs[L], BEs[L]);
        if (L < 2) {
            apply_kernel<<<AB, 256>>>(f_hpre, (float*)p_h);
            layer_in = f_h;
        } else {
            apply3_pool_kernel<<<AB, 256>>>(batch, f_hpre, f_sc);
        }
    }

    final_kernel<<<Gg, 64>>>(w_lin, b_lin, out);
}

// round 11
// speedup vs baseline: 1.9283x; 1.1090x over previous
#include <cuda_runtime.h>
#include <cstdint>
#include <cstdio>

// Problem constants (fixed by the reference)
#define Nn 100000
#define Ee 1600000
#define Hh 64
#define Gg 64

// ---------------- static device scratch (no allocations allowed) ----------------
__device__ int      g_cnt[Nn];        // per-row edge count
__device__ int      g_ptr[Nn + 1];    // CSR row pointers
__device__ int      g_fill[Nn];       // scatter cursors
__device__ float    g_dis[Nn];        // deg^{-1/2}
__device__ int      g_ccol[Ee];       // CSR col indices
__device__ float    g_cnorm[Ee];      // CSR edge weights (-dis[r]*dis[c])
__device__ float    g_T1 [Nn * Hh];
__device__ float    g_Tmp[Nn * Hh];
__device__ float    g_hpre[Nn * Hh];
__device__ float    g_h  [Nn * Hh];
__device__ float    g_sc [Nn * Hh];
__device__ float    g_Wc [192 * 64];
__device__ float    g_stats[128];     // [0:64) sum, [64:128) sumsq
__device__ float    g_ab[128];        // [0:64) scale a, [64:128) shift c
__device__ unsigned g_pool[Gg * 64];

// ---------------- helpers ----------------
__device__ __forceinline__ unsigned enc_f(float f) {
    unsigned u = __float_as_uint(f);
    return (u & 0x80000000u) ? ~u : (u | 0x80000000u);
}
__device__ __forceinline__ float dec_f(unsigned u) {
    return (u & 0x80000000u) ? __uint_as_float(u & 0x7FFFFFFFu) : __uint_as_float(~u);
}
__device__ __forceinline__ float lrelu(float x) { return x > 0.0f ? x : 0.01f * x; }

// ---------------- preprocessing: CSR build ----------------
// edge_index is int32, layout [2, E] row-major.
__global__ void count_kernel(const int* __restrict__ ei) {
    int i = blockIdx.x * blockDim.x + threadIdx.x;
    if (i >= Ee) return;
    atomicAdd(&g_cnt[ei[i]], 1);
}

// Single-block exclusive scan of g_cnt -> g_ptr, g_fill; also g_dis = cnt^{-1/2}.
__global__ void __launch_bounds__(1024) scan_kernel() {
    const int T = 1024;
    const int C = (Nn + T - 1) / T;  // 98
    int t = threadIdx.x;
    int base = t * C;
    int s = 0;
    for (int i = 0; i < C; i++) {
        int idx = base + i;
        if (idx < Nn) s += g_cnt[idx];
    }
    __shared__ int sh[T];
    sh[t] = s;
    __syncthreads();
    for (int off = 1; off < T; off <<= 1) {
        int v = (t >= off) ? sh[t - off] : 0;
        __syncthreads();
        sh[t] += v;
        __syncthreads();
    }
    int run = (t == 0) ? 0 : sh[t - 1];
    for (int i = 0; i < C; i++) {
        int idx = base + i;
        if (idx < Nn) {
            int cnt = g_cnt[idx];
            g_ptr[idx] = run;
            g_fill[idx] = run;
            g_dis[idx] = cnt > 0 ? rsqrtf((float)cnt) : 0.0f;
            run += cnt;
        }
    }
    if (t == T - 1) g_ptr[Nn] = run;  // == Ee
}

__global__ void scatter_kernel(const int* __restrict__ ei) {
    int i = blockIdx.x * blockDim.x + threadIdx.x;
    if (i >= Ee) return;
    int r = ei[i];
    int c = ei[Ee + i];
    int pos = atomicAdd(&g_fill[r], 1);
    g_ccol[pos] = c;
    g_cnorm[pos] = -g_dis[r] * g_dis[c];
}

// ---------------- CSR propagation: dst[r] = sum_e norm[e] * src[col[e]] ----------------
// 16 threads per row (one float4 each); unroll-4 on edges (validated: 35 us).
__global__ void __launch_bounds__(256) prop_csr_kernel(const float* __restrict__ src,
                                                       float* __restrict__ dst) {
    int r = blockIdx.x * 16 + (threadIdx.x >> 4);
    int q = threadIdx.x & 15;
    if (r >= Nn) return;
    int s = g_ptr[r];
    int e = g_ptr[r + 1];
    const float4* __restrict__ src4 = reinterpret_cast<const float4*>(src);
    float4 acc = make_float4(0.f, 0.f, 0.f, 0.f);
    int i = s;
    for (; i + 4 <= e; i += 4) {
        int   c0 = __ldg(&g_ccol[i]),     c1 = __ldg(&g_ccol[i + 1]);
        int   c2 = __ldg(&g_ccol[i + 2]), c3 = __ldg(&g_ccol[i + 3]);
        float n0 = __ldg(&g_cnorm[i]),     n1 = __ldg(&g_cnorm[i + 1]);
        float n2 = __ldg(&g_cnorm[i + 2]), n3 = __ldg(&g_cnorm[i + 3]);
        float4 v0 = __ldg(&src4[c0 * 16 + q]);
        float4 v1 = __ldg(&src4[c1 * 16 + q]);
        float4 v2 = __ldg(&src4[c2 * 16 + q]);
        float4 v3 = __ldg(&src4[c3 * 16 + q]);
        acc.x += n0 * v0.x + n1 * v1.x + n2 * v2.x + n3 * v3.x;
        acc.y += n0 * v0.y + n1 * v1.y + n2 * v2.y + n3 * v3.y;
        acc.z += n0 * v0.z + n1 * v1.z + n2 * v2.z + n3 * v3.z;
        acc.w += n0 * v0.w + n1 * v1.w + n2 * v2.w + n3 * v3.w;
    }
    for (; i < e; i++) {
        int   c = __ldg(&g_ccol[i]);
        float n = __ldg(&g_cnorm[i]);
        float4 v = __ldg(&src4[c * 16 + q]);
        acc.x += n * v.x;
        acc.y += n * v.y;
        acc.z += n * v.z;
        acc.w += n * v.w;
    }
    reinterpret_cast<float4*>(dst)[r * 16 + q] = acc;
}

// ---------------- combined ChebConv weight ----------------
// out = Tx0@(W0 - W2) + Tx1@W1 + prop(Tx1)@(2*W2)
__global__ void combine_wc_kernel(const float* __restrict__ w) {
    int idx = blockIdx.x * blockDim.x + threadIdx.x;
    if (idx >= 192 * 64) return;
    int kk = idx >> 6, j = idx & 63;
    float v;
    if (kk < 64)        v = w[kk * 64 + j] - w[2 * 4096 + kk * 64 + j];
    else if (kk < 128)  v = w[4096 + (kk - 64) * 64 + j];
    else                v = 2.0f * w[2 * 4096 + (kk - 128) * 64 + j];
    g_Wc[idx] = v;
}

// ---------------- fused 3-term GEMM, 8x8 register tiling ----------------
// 256 threads, 256 rows/block. Thread (ry, cx): rows ry*8..ry*8+7, cols cx*8..cx*8+7.
// X staged TRANSPOSED in smem: sX[k][row] -> v-load = 2 LDS.128, conflict-free.
// Per k: 4 LDS.128 + 64 FFMA  =>  ~94% FFMA instruction stream.
// Dynamic smem: sW 192*64 f (48 KB) + sX 64*256 f (64 KB) = 114688 B.
__global__ void __launch_bounds__(256, 2) gemm3_kernel(const float* __restrict__ s0,
                                                       const float* __restrict__ s1,
                                                       const float* __restrict__ s2,
                                                       const float* __restrict__ bias,
                                                       float* __restrict__ out) {
    extern __shared__ float dyn[];
    float* sW = dyn;               // [k 0..191][col 0..63]
    float* sX = dyn + 192 * 64;    // [k 0..63][row 0..255]
    int tid = threadIdx.x;

    // stage W (natural layout == g_Wc layout)
    const float4* gW = reinterpret_cast<const float4*>(g_Wc);
    float4* sW4 = reinterpret_cast<float4*>(sW);
#pragma unroll
    for (int i = 0; i < 12; i++) sW4[tid + 256 * i] = gW[tid + 256 * i];

    int ry = tid >> 3;   // 0..31 row-tile (8 rows each)
    int cx = tid & 7;    // 0..7 col-tile (8 cols each)
    int rowBase = blockIdx.x * 256;

    float acc[8][8];
#pragma unroll
    for (int j = 0; j < 8; j++) {
        float b = __ldg(&bias[cx * 8 + j]);
#pragma unroll
        for (int i = 0; i < 8; i++) acc[i][j] = b;
    }

    const float* srcs[3] = {s0, s1, s2};
#pragma unroll 1
    for (int s = 0; s < 3; s++) {
        __syncthreads();   // previous compute done (and sW staged on s=0)
        // stage source s transposed: thread stages row rowBase+tid
        {
            int r = rowBase + tid;
            const float4* p = reinterpret_cast<const float4*>(srcs[s] + (size_t)r * 64);
            bool ok = r < Nn;
#pragma unroll
            for (int k4 = 0; k4 < 16; k4++) {
                float4 v = ok ? __ldg(&p[k4]) : make_float4(0.f, 0.f, 0.f, 0.f);
                sX[(k4 * 4 + 0) * 256 + tid] = v.x;
                sX[(k4 * 4 + 1) * 256 + tid] = v.y;
                sX[(k4 * 4 + 2) * 256 + tid] = v.z;
                sX[(k4 * 4 + 3) * 256 + tid] = v.w;
            }
        }
        __syncthreads();
#pragma unroll 1
        for (int k = 0; k < 64; k++) {
            float4 va = *reinterpret_cast<const float4*>(&sX[k * 256 + ry * 8]);
            float4 vb = *reinterpret_cast<const float4*>(&sX[k * 256 + ry * 8 + 4]);
            float4 wa = *reinterpret_cast<const float4*>(&sW[(s * 64 + k) * 64 + cx * 8]);
            float4 wb = *reinterpret_cast<const float4*>(&sW[(s * 64 + k) * 64 + cx * 8 + 4]);
            float v[8] = {va.x, va.y, va.z, va.w, vb.x, vb.y, vb.z, vb.w};
            float w[8] = {wa.x, wa.y, wa.z, wa.w, wb.x, wb.y, wb.z, wb.w};
#pragma unroll
            for (int i = 0; i < 8; i++)
#pragma unroll
                for (int j = 0; j < 8; j++)
                    acc[i][j] += v[i] * w[j];
        }
    }
#pragma unroll
    for (int i = 0; i < 8; i++) {
        int r = rowBase + ry * 8 + i;
        if (r < Nn) {
            float4* po = reinterpret_cast<float4*>(out + (size_t)r * 64 + cx * 8);
            po[0] = make_float4(acc[i][0], acc[i][1], acc[i][2], acc[i][3]);
            po[1] = make_float4(acc[i][4], acc[i][5], acc[i][6], acc[i][7]);
        }
    }
}

// ---------------- shortcut GEMM, 8x8 register tiling: out = x @ W(64x64) + bias ----------------
// Dynamic smem: sW 64*64 f (16 KB) + sX 64*256 f (64 KB) = 81920 B.
__global__ void __launch_bounds__(256, 2) gemm1_kernel(const float* __restrict__ s0,
                                                       const float* __restrict__ wsc,
                                                       const float* __restrict__ bias,
                                                       float* __restrict__ out) {
    extern __shared__ float dyn[];
    float* sW = dyn;               // [k 0..63][col 0..63]
    float* sX = dyn + 64 * 64;     // [k 0..63][row 0..255]
    int tid = threadIdx.x;

    const float4* gW = reinterpret_cast<const float4*>(wsc);
    float4* sW4 = reinterpret_cast<float4*>(sW);
#pragma unroll
    for (int i = 0; i < 4; i++) sW4[tid + 256 * i] = __ldg(&gW[tid + 256 * i]);

    int ry = tid >> 3;
    int cx = tid & 7;
    int rowBase = blockIdx.x * 256;

    float acc[8][8];
#pragma unroll
    for (int j = 0; j < 8; j++) {
        float b = __ldg(&bias[cx * 8 + j]);
#pragma unroll
        for (int i = 0; i < 8; i++) acc[i][j] = b;
    }

    {
        int r = rowBase + tid;
        const float4* p = reinterpret_cast<const float4*>(s0 + (size_t)r * 64);
        bool ok = r < Nn;
#pragma unroll
        for (int k4 = 0; k4 < 16; k4++) {
            float4 v = ok ? __ldg(&p[k4]) : make_float4(0.f, 0.f, 0.f, 0.f);
            sX[(k4 * 4 + 0) * 256 + tid] = v.x;
            sX[(k4 * 4 + 1) * 256 + tid] = v.y;
            sX[(k4 * 4 + 2) * 256 + tid] = v.z;
            sX[(k4 * 4 + 3) * 256 + tid] = v.w;
        }
    }
    __syncthreads();

#pragma unroll 1
    for (int k = 0; k < 64; k++) {
        float4 va = *reinterpret_cast<const float4*>(&sX[k * 256 + ry * 8]);
        float4 vb = *reinterpret_cast<const float4*>(&sX[k * 256 + ry * 8 + 4]);
        float4 wa = *reinterpret_cast<const float4*>(&sW[k * 64 + cx * 8]);
        float4 wb = *reinterpret_cast<const float4*>(&sW[k * 64 + cx * 8 + 4]);
        float v[8] = {va.x, va.y, va.z, va.w, vb.x, vb.y, vb.z, vb.w};
        float w[8] = {wa.x, wa.y, wa.z, wa.w, wb.x, wb.y, wb.z, wb.w};
#pragma unroll
        for (int i = 0; i < 8; i++)
#pragma unroll
            for (int j = 0; j < 8; j++)
                acc[i][j] += v[i] * w[j];
    }
#pragma unroll
    for (int i = 0; i < 8; i++) {
        int r = rowBase + ry * 8 + i;
        if (r < Nn) {
            float4* po = reinterpret_cast<float4*>(out + (size_t)r * 64 + cx * 8);
            po[0] = make_float4(acc[i][0], acc[i][1], acc[i][2], acc[i][3]);
            po[1] = make_float4(acc[i][4], acc[i][5], acc[i][6], acc[i][7]);
        }
    }
}

// ---------------- BN statistics (R4-proven scalar form) ----------------
__global__ void __launch_bounds__(256) stats_kernel(const float* __restrict__ h) {
    int j = threadIdx.x & 63;
    int r0 = blockIdx.x * 4 + (threadIdx.x >> 6);
    float s = 0.0f, s2 = 0.0f;
    for (int r = r0; r < Nn; r += gridDim.x * 4) {
        float v = h[(size_t)r * 64 + j];
        s += v;
        s2 += v * v;
    }
    __shared__ float sh[256], sh2[256];
    sh[threadIdx.x] = s;
    sh2[threadIdx.x] = s2;
    __syncthreads();
    if (threadIdx.x < 64) {
        float ts  = sh[threadIdx.x] + sh[threadIdx.x + 64] + sh[threadIdx.x + 128] + sh[threadIdx.x + 192];
        float ts2 = sh2[threadIdx.x] + sh2[threadIdx.x + 64] + sh2[threadIdx.x + 128] + sh2[threadIdx.x + 192];
        atomicAdd(&g_stats[j], ts);
        atomicAdd(&g_stats[64 + j], ts2);
    }
}

__global__ void finalize_kernel(const float* __restrict__ gamma,
                                const float* __restrict__ beta) {
    int j = threadIdx.x;
    if (j >= 64) return;
    float mu  = g_stats[j] * (1.0f / (float)Nn);
    float var = g_stats[64 + j] * (1.0f / (float)Nn) - mu * mu;
    var = fmaxf(var, 0.0f);
    float a = gamma[j] * rsqrtf(var + 1e-5f);
    g_ab[j] = a;
    g_ab[64 + j] = beta[j] - mu * a;
}

// ---------------- BN apply + LeakyReLU (layers 1 & 2) ----------------
__global__ void __launch_bounds__(256) apply_kernel(const float* __restrict__ hpre,
                                                    float* __restrict__ h) {
    int idx = blockIdx.x * blockDim.x + threadIdx.x;  // Nn*16 float4
    if (idx >= Nn * 16) return;
    int j4 = idx & 15;
    float4 a = reinterpret_cast<const float4*>(g_ab)[j4];
    float4 c = reinterpret_cast<const float4*>(g_ab + 64)[j4];
    float4 v = reinterpret_cast<const float4*>(hpre)[idx];
    float4 o;
    o.x = lrelu(v.x * a.x + c.x);
    o.y = lrelu(v.y * a.y + c.y);
    o.z = lrelu(v.z * a.z + c.z);
    o.w = lrelu(v.w * a.w + c.w);
    reinterpret_cast<float4*>(h)[idx] = o;
}

// ---------------- layer 3: BN apply + LeakyReLU + shortcut + segment_max pooling ----------------
__global__ void __launch_bounds__(256) apply3_pool_kernel(const int* __restrict__ batch,
                                                          const float* __restrict__ hpre,
                                                          const float* __restrict__ sc) {
    int idx = blockIdx.x * 256 + threadIdx.x;  // exactly Nn*16 = 6250 blocks
    int j4 = idx & 15;
    int r = idx >> 4;
    float4 a = reinterpret_cast<const float4*>(g_ab)[j4];
    float4 c = reinterpret_cast<const float4*>(g_ab + 64)[j4];
    float4 v = reinterpret_cast<const float4*>(hpre)[idx];
    float4 s = reinterpret_cast<const float4*>(sc)[idx];
    float4 h;
    h.x = lrelu(v.x * a.x + c.x) + s.x;
    h.y = lrelu(v.y * a.y + c.y) + s.y;
    h.z = lrelu(v.z * a.z + c.z) + s.z;
    h.w = lrelu(v.w * a.w + c.w) + s.w;

    __shared__ float4 sv[256];
    sv[threadIdx.x] = h;
    int row0 = blockIdx.x * 16;
    __syncthreads();

    int b0 = batch[row0];
    int bL = batch[row0 + 15];
    if (b0 == bL) {
        if (threadIdx.x < 64) {
            int slot = threadIdx.x;
            const float* svf = reinterpret_cast<const float*>(sv);
            float m = svf[slot];
#pragma unroll
            for (int rr = 1; rr < 16; rr++) m = fmaxf(m, svf[rr * 64 + slot]);
            atomicMax(&g_pool[b0 * 64 + slot], enc_f(m));
        }
    } else {
        int b = batch[r];
        atomicMax(&g_pool[b * 64 + j4 * 4 + 0], enc_f(h.x));
        atomicMax(&g_pool[b * 64 + j4 * 4 + 1], enc_f(h.y));
        atomicMax(&g_pool[b * 64 + j4 * 4 + 2], enc_f(h.z));
        atomicMax(&g_pool[b * 64 + j4 * 4 + 3], enc_f(h.w));
    }
}

// ---------------- final: out[g] = pooled[g,:] @ w_lin + b_lin ----------------
__global__ void final_kernel(const float* __restrict__ wl,
                             const float* __restrict__ bl,
                             float* __restrict__ out) {
    int g = blockIdx.x;
    int j = threadIdx.x;
    float v = dec_f(g_pool[g * 64 + j]) * wl[j];
    __shared__ float sred[64];
    sred[j] = v;
    __syncthreads();
    if (j < 32) {
        float t = sred[j] + sred[j + 32];
#pragma unroll
        for (int off = 16; off > 0; off >>= 1) t += __shfl_down_sync(0xFFFFFFFFu, t, off);
        if (j == 0) out[g] = t + bl[0];
    }
}

// ---------------- host launcher ----------------
extern "C" void kernel_launch(void* const* d_in, const int* in_sizes, int n_in,
                              void* d_out, int out_size) {
    (void)in_sizes; (void)n_in; (void)out_size;
    const float* x     = (const float*)d_in[0];
    const int*   ei    = (const int*)d_in[1];      // int32 (JAX x64 disabled)
    const int*   batch = (const int*)d_in[2];      // int32
    const float* w1 = (const float*)d_in[3];
    const float* b1 = (const float*)d_in[4];
    const float* w2 = (const float*)d_in[5];
    const float* b2 = (const float*)d_in[6];
    const float* w3 = (const float*)d_in[7];
    const float* b3 = (const float*)d_in[8];
    const float* g1 = (const float*)d_in[9];
    const float* be1 = (const float*)d_in[10];
    const float* g2 = (const float*)d_in[11];
    const float* be2 = (const float*)d_in[12];
    const float* g3 = (const float*)d_in[13];
    const float* be3 = (const float*)d_in[14];
    const float* w_sc = (const float*)d_in[15];
    const float* b_sc = (const float*)d_in[16];
    const float* w_lin = (const float*)d_in[17];
    const float* b_lin = (const float*)d_in[18];
    float* out = (float*)d_out;

    // Opt-in dynamic smem (host-side attribute set; capture-safe, idempotent)
    cudaFuncSetAttribute(gemm3_kernel, cudaFuncAttributeMaxDynamicSharedMemorySize, 114688);
    cudaFuncSetAttribute(gemm1_kernel, cudaFuncAttributeMaxDynamicSharedMemorySize, 81920);

    void *p_cnt, *p_T1, *p_Tmp, *p_hpre, *p_h, *p_sc, *p_stats, *p_pool;
    cudaGetSymbolAddress(&p_cnt, g_cnt);
    cudaGetSymbolAddress(&p_T1, g_T1);
    cudaGetSymbolAddress(&p_Tmp, g_Tmp);
    cudaGetSymbolAddress(&p_hpre, g_hpre);
    cudaGetSymbolAddress(&p_h, g_h);
    cudaGetSymbolAddress(&p_sc, g_sc);
    cudaGetSymbolAddress(&p_stats, g_stats);
    cudaGetSymbolAddress(&p_pool, g_pool);

    const float* f_T1   = (const float*)p_T1;
    const float* f_Tmp  = (const float*)p_Tmp;
    const float* f_hpre = (const float*)p_hpre;
    const float* f_h    = (const float*)p_h;
    const float* f_sc   = (const float*)p_sc;

    const int EB = (Ee + 255) / 256;          // 6250
    const int GB = (Nn + 255) / 256;          // 391 (GEMMs: 256 rows/block)
    const int RB = Nn / 16;                   // 6250 (prop: 16 rows/block)
    const int AB = (Nn * 16 + 255) / 256;     // 6250

    // --- CSR build; gemm1 sits at profiled launch slot 5 ---
    cudaMemsetAsync(p_cnt, 0, Nn * sizeof(int));
    count_kernel<<<EB, 256>>>(ei);
    scan_kernel<<<1, 1024>>>();
    scatter_kernel<<<EB, 256>>>(ei);
    gemm1_kernel<<<GB, 256, 81920>>>(x, w_sc, b_sc, (float*)p_sc);
    cudaMemsetAsync(p_pool, 0, Gg * 64 * sizeof(unsigned));

    const float* layer_in = x;
    const float* Ws[3] = {w1, w2, w3};
    const float* Bs[3] = {b1, b2, b3};
    const float* Gs[3] = {g1, g2, g3};
    const float* BEs[3] = {be1, be2, be3};

    for (int L = 0; L < 3; L++) {
        prop_csr_kernel<<<RB, 256>>>(layer_in, (float*)p_T1);
        prop_csr_kernel<<<RB, 256>>>(f_T1, (float*)p_Tmp);
        combine_wc_kernel<<<48, 256>>>(Ws[L]);
        gemm3_kernel<<<GB, 256, 114688>>>(layer_in, f_T1, f_Tmp, Bs[L], (float*)p_hpre);
        cudaMemsetAsync(p_stats, 0, 128 * sizeof(float));
        stats_kernel<<<256, 256>>>(f_hpre);
        finalize_kernel<<<1, 64>>>(Gs[L], BEs[L]);
        if (L < 2) {
            apply_kernel<<<AB, 256>>>(f_hpre, (float*)p_h);
            layer_in = f_h;
        } else {
            apply3_pool_kernel<<<AB, 256>>>(batch, f_hpre, f_sc);
        }
    }

    final_kernel<<<Gg, 64>>>(w_lin, b_lin, out);
}